// round 16
// baseline (speedup 1.0000x reference)
#include <cuda_runtime.h>
#include <cstdint>

// SPDUnVectorize: x[B, L] packed upper triangle (row-major, incl. diag) ->
// out[B, n, n] symmetric. B=1024, n=256, L=n(n+1)/2=32896.
//
// Champion config (R10) with uniform v8 store path:
//  - one block = one 32x32 tile x 2 batches, 18432 blocks
//  - 8 register-staged, fully-coalesced LDGs per thread (warp = row)
//  - upper tile stored DIRECTLY from load registers before the barrier
//  - single __syncthreads(); mirror AND diagonal emit via PAD-33 smem,
//    one 256-bit store per thread (warp = 8 consecutive full 128B rows)

#define NMAT   256
#define L_IN   32896
#define BATCH  1024
#define TILE   32
#define NTROW  8
#define NTILES 36
#define PAD    33

__device__ __forceinline__ int tri_off(int r) {
    return r * NMAT - (r * (r - 1)) / 2;
}

__device__ __forceinline__ void stg256(float* p, const float* v) {
    asm volatile(
        "st.global.v8.b32 [%0], {%1, %2, %3, %4, %5, %6, %7, %8};"
        :: "l"(p),
           "r"(__float_as_uint(v[0])), "r"(__float_as_uint(v[1])),
           "r"(__float_as_uint(v[2])), "r"(__float_as_uint(v[3])),
           "r"(__float_as_uint(v[4])), "r"(__float_as_uint(v[5])),
           "r"(__float_as_uint(v[6])), "r"(__float_as_uint(v[7]))
        : "memory");
}

__global__ __launch_bounds__(256, 7)
void spd_unvec_kernel(const float* __restrict__ in, float* __restrict__ out) {
    __shared__ float s0[TILE][PAD];
    __shared__ float s1[TILE][PAD];

    const int b0 = blockIdx.y * 2;
    int t = blockIdx.x;

    int ti = 0;
    int rem = NTROW;
    while (t >= rem) { t -= rem; rem--; ti++; }
    const int tj = ti + t;

    const int lane = threadIdx.x & 31;   // column within tile (loads/upper)
    const int wy   = threadIdx.x >> 5;   // 0..7 (base row)

    const float* __restrict__ in0  = in  + (size_t)b0 * L_IN;
    const float* __restrict__ in1  = in0 + L_IN;
    float*       __restrict__ out0 = out + (size_t)b0 * (NMAT * NMAT);
    float*       __restrict__ out1 = out0 + (NMAT * NMAT);

    // v8 emit mapping: 256 threads -> 2 batches x 32 rows x 4 chunks
    const int mb   = threadIdx.x >> 7;           // 0..1 batch
    const int mrow = (threadIdx.x >> 2) & 31;    // 0..31 row
    const int moc  = (threadIdx.x & 3) << 3;     // 0,8,16,24

    if (ti == tj) {
        // ---- Diagonal tile, both batches (8/36 tiles) ----
        #pragma unroll
        for (int k = 0; k < 4; k++) {
            const int lr = wy + k * 8;
            const int r  = ti * TILE + lr;
            if (lane >= lr) {
                const int idx = tri_off(r) + lane - lr;
                s0[lr][lane] = in0[idx];
                s1[lr][lane] = in1[idx];
            }
        }
        __syncthreads();
        // Emit full tile: select upper/transposed, one v8 store per thread.
        const int R = ti * TILE;
        float m[8];
        if (mb == 0) {
            #pragma unroll
            for (int k = 0; k < 8; k++) {
                const int c = moc + k;
                m[k] = (c >= mrow) ? s0[mrow][c] : s0[c][mrow];
            }
            stg256(&out0[(R + mrow) * NMAT + R + moc], m);
        } else {
            #pragma unroll
            for (int k = 0; k < 8; k++) {
                const int c = moc + k;
                m[k] = (c >= mrow) ? s1[mrow][c] : s1[c][mrow];
            }
            stg256(&out1[(R + mrow) * NMAT + R + moc], m);
        }
    } else {
        // ---- Off-diagonal tile (ti < tj), both batches ----
        // Stage all 8 loads (4 rows x 2 batches) in registers first.
        float v0[4], v1[4];
        #pragma unroll
        for (int k = 0; k < 4; k++) {
            const int lr  = wy + k * 8;
            const int r   = ti * TILE + lr;
            const int idx = tri_off(r) - r + tj * TILE + lane;
            v0[k] = in0[idx];
            v1[k] = in1[idx];
        }
        // Upper tile: store DIRECTLY from registers before the barrier.
        #pragma unroll
        for (int k = 0; k < 4; k++) {
            const int lr = wy + k * 8;
            const int r  = ti * TILE + lr;
            out0[r * NMAT + tj * TILE + lane] = v0[k];
            out1[r * NMAT + tj * TILE + lane] = v1[k];
            s0[lr][lane] = v0[k];
            s1[lr][lane] = v1[k];
        }
        __syncthreads();

        // Mirror tile: one 256-bit store per thread.
        float m[8];
        if (mb == 0) {
            #pragma unroll
            for (int k = 0; k < 8; k++) m[k] = s0[moc + k][mrow];
            stg256(&out0[(tj * TILE + mrow) * NMAT + ti * TILE + moc], m);
        } else {
            #pragma unroll
            for (int k = 0; k < 8; k++) m[k] = s1[moc + k][mrow];
            stg256(&out1[(tj * TILE + mrow) * NMAT + ti * TILE + moc], m);
        }
    }
}

extern "C" void kernel_launch(void* const* d_in, const int* in_sizes, int n_in,
                              void* d_out, int out_size) {
    const float* in = (const float*)d_in[0];
    float* out = (float*)d_out;
    dim3 grid(NTILES, BATCH / 2);
    dim3 block(256);
    spd_unvec_kernel<<<grid, block>>>(in, out);
}

// round 17
// speedup vs baseline: 1.0258x; 1.0258x over previous
#include <cuda_runtime.h>
#include <cstdint>

// SPDUnVectorize: x[B, L] packed upper triangle (row-major, incl. diag) ->
// out[B, n, n] symmetric. B=1024, n=256, L=n(n+1)/2=32896.
//
// FINAL — record-holding configuration (R10: 61.9us wall, 57.9us kernel,
// DRAM 75.2% ~6.0TB/s, occ 93%):
//  - one block = one 32x32 upper-triangle tile x 2 batches (18432 blocks)
//  - 8 register-staged, fully-coalesced LDGs per thread (warp = row)
//  - upper tile stored DIRECTLY from load registers before the barrier
//  - single __syncthreads(); mirror via PAD-33 smem, 256-bit stores
// Ceiling analysis: traffic is exactly minimal (346MB); DRAM-active pinned
// at 74-76% across occ 69-93%, MLP 8-16/thread, block 128/256, barrier and
// store-width variants -> mixed read/write DRAM stream efficiency is the
// binding limit. Cache hints (__ldcs/__stcs) measurably regress on sm_103a.

#define NMAT   256
#define L_IN   32896
#define BATCH  1024
#define TILE   32
#define NTROW  8
#define NTILES 36
#define PAD    33

__device__ __forceinline__ int tri_off(int r) {
    return r * NMAT - (r * (r - 1)) / 2;
}

__device__ __forceinline__ void stg256(float* p, const float* v) {
    asm volatile(
        "st.global.v8.b32 [%0], {%1, %2, %3, %4, %5, %6, %7, %8};"
        :: "l"(p),
           "r"(__float_as_uint(v[0])), "r"(__float_as_uint(v[1])),
           "r"(__float_as_uint(v[2])), "r"(__float_as_uint(v[3])),
           "r"(__float_as_uint(v[4])), "r"(__float_as_uint(v[5])),
           "r"(__float_as_uint(v[6])), "r"(__float_as_uint(v[7]))
        : "memory");
}

__global__ __launch_bounds__(256, 7)
void spd_unvec_kernel(const float* __restrict__ in, float* __restrict__ out) {
    __shared__ float s0[TILE][PAD];
    __shared__ float s1[TILE][PAD];

    const int b0 = blockIdx.y * 2;
    int t = blockIdx.x;

    int ti = 0;
    int rem = NTROW;
    while (t >= rem) { t -= rem; rem--; ti++; }
    const int tj = ti + t;

    const int lane = threadIdx.x & 31;   // column within tile (loads/upper)
    const int wy   = threadIdx.x >> 5;   // 0..7 (base row)

    const float* __restrict__ in0  = in  + (size_t)b0 * L_IN;
    const float* __restrict__ in1  = in0 + L_IN;
    float*       __restrict__ out0 = out + (size_t)b0 * (NMAT * NMAT);
    float*       __restrict__ out1 = out0 + (NMAT * NMAT);

    if (ti == tj) {
        // ---- Diagonal tile, both batches (8/36 tiles) ----
        #pragma unroll
        for (int k = 0; k < 4; k++) {
            const int lr = wy + k * 8;
            const int r  = ti * TILE + lr;
            if (lane >= lr) {
                const int idx = tri_off(r) + lane - lr;
                s0[lr][lane] = in0[idx];
                s1[lr][lane] = in1[idx];
            }
        }
        __syncthreads();
        const int row = threadIdx.x >> 3;
        const int qc  = (threadIdx.x & 7) << 2;
        const int r   = ti * TILE + row;
        float4 v0, v1;
        #pragma unroll
        for (int k = 0; k < 4; k++) {
            const int c  = qc + k;
            const bool up = (c >= row);
            ((float*)&v0)[k] = up ? s0[row][c] : s0[c][row];
            ((float*)&v1)[k] = up ? s1[row][c] : s1[c][row];
        }
        *reinterpret_cast<float4*>(&out0[r * NMAT + ti * TILE + qc]) = v0;
        *reinterpret_cast<float4*>(&out1[r * NMAT + ti * TILE + qc]) = v1;
    } else {
        // ---- Off-diagonal tile (ti < tj), both batches ----
        // Stage all 8 loads (4 rows x 2 batches) in registers first.
        float v0[4], v1[4];
        #pragma unroll
        for (int k = 0; k < 4; k++) {
            const int lr  = wy + k * 8;
            const int r   = ti * TILE + lr;
            const int idx = tri_off(r) - r + tj * TILE + lane;
            v0[k] = in0[idx];
            v1[k] = in1[idx];
        }
        // Upper tile: store DIRECTLY from registers before the barrier.
        #pragma unroll
        for (int k = 0; k < 4; k++) {
            const int lr = wy + k * 8;
            const int r  = ti * TILE + lr;
            out0[r * NMAT + tj * TILE + lane] = v0[k];
            out1[r * NMAT + tj * TILE + lane] = v1[k];
            s0[lr][lane] = v0[k];
            s1[lr][lane] = v1[k];
        }
        __syncthreads();

        // Mirror tile: one 256-bit store per thread.
        const int mb   = threadIdx.x >> 7;           // 0..1 batch
        const int mrow = (threadIdx.x >> 2) & 31;    // 0..31 mirror row
        const int moc  = (threadIdx.x & 3) << 3;     // 0,8,16,24

        float m[8];
        if (mb == 0) {
            #pragma unroll
            for (int k = 0; k < 8; k++) m[k] = s0[moc + k][mrow];
            stg256(&out0[(tj * TILE + mrow) * NMAT + ti * TILE + moc], m);
        } else {
            #pragma unroll
            for (int k = 0; k < 8; k++) m[k] = s1[moc + k][mrow];
            stg256(&out1[(tj * TILE + mrow) * NMAT + ti * TILE + moc], m);
        }
    }
}

extern "C" void kernel_launch(void* const* d_in, const int* in_sizes, int n_in,
                              void* d_out, int out_size) {
    const float* in = (const float*)d_in[0];
    float* out = (float*)d_out;
    dim3 grid(NTILES, BATCH / 2);
    dim3 block(256);
    spd_unvec_kernel<<<grid, block>>>(in, out);
}